// round 4
// baseline (speedup 1.0000x reference)
#include <cuda_runtime.h>
#include <cstdint>

// Spiking1DLIFLayer: B=128, C=512, T=1024  (row=(b,c), serial recurrence over T)
//   mem = (mem*beta + x[t]) - spk_prev*Vth[c] ;  spk = mem > Vth[c]
// Pure HBM-bound stream (256MB in + 256MB out).
// R4: write-through (st.global.wt) spike stores — each output line is written
// exactly once and never re-read, so L2 dirty-accumulation only hurts: in
// graph-replay steady state the previous launch's ~100MB dirty backlog drains
// into the next launch's read burst. .wt drains writes continuously instead.
// Pipeline: 1 warp/block, cp.async.cg triple-buffered, conflict-free smem.
// Numerics bit-identical to reference (rel_err 0.0 in R1-R3).

#define Bdim 128
#define Cdim 512
#define Tdim 1024
#define NT    32                 // threads per block == rows per block (1 warp)
#define TS    32                 // time-tile (floats)
#define F4    (TS / 4)           // 8 float4 per row per tile
#define PITCH (F4 + 1)           // 9 float4 -> conflict-free row access
#define NBUF  3
#define NTILES (Tdim / TS)       // 32

__device__ __forceinline__ void cp16(uint32_t dst_smem, const float4* src) {
    asm volatile("cp.async.cg.shared.global [%0], [%1], 16;\n"
                 :: "r"(dst_smem), "l"(src));
}
__device__ __forceinline__ void cp_commit() {
    asm volatile("cp.async.commit_group;\n");
}
__device__ __forceinline__ void cp_wait2() {
    asm volatile("cp.async.wait_group 2;\n");
}
__device__ __forceinline__ void stwt(float4* p, float4 v) {
    asm volatile("st.global.wt.v4.f32 [%0], {%1, %2, %3, %4};\n"
                 :: "l"(p), "f"(v.x), "f"(v.y), "f"(v.z), "f"(v.w)
                 : "memory");
}

__global__ void __launch_bounds__(NT, 16)
lif_kernel(const float* __restrict__ x,
           const float* __restrict__ beta_p,
           const float* __restrict__ vth_p,
           float* __restrict__ out)
{
    __shared__ float4 tile[NBUF][NT * PITCH];

    const int tid = threadIdx.x;
    const int r0  = blockIdx.x * NT;
    const float beta = __ldg(beta_p);
    const float vth  = __ldg(vth_p + ((r0 + tid) & (Cdim - 1)));

    const float4* __restrict__ xg = (const float4*)x;
    float4* __restrict__ og = (float4*)out;
    const int row_f4 = Tdim / 4;                  // 256 float4 per global row

    // ---- prologue: preload tiles 0..2 ----
    #pragma unroll
    for (int p = 0; p < NBUF; ++p) {
        const int tcol0 = p * F4;
        uint32_t sbase = (uint32_t)__cvta_generic_to_shared(&tile[p][0]);
        #pragma unroll
        for (int i = 0; i < F4; ++i) {
            int idx = i * NT + tid;
            int row = idx >> 3;                   // idx / F4
            int col = idx & 7;                    // idx % F4
            cp16(sbase + (uint32_t)(row * PITCH + col) * 16u,
                 xg + (size_t)(r0 + row) * row_f4 + tcol0 + col);
        }
        cp_commit();
    }

    float mem = 0.0f;
    float rst = 0.0f;
    int b = 0;

    for (int it = 0; it < NTILES; ++it) {
        cp_wait2();                               // tile `it` landed
        __syncthreads();                          // nw=1: cheap, warp-visibility

        // ---- recurrence: thread owns row `tid`, 32 steps from smem ----
        float4* mybuf = &tile[b][tid * PITCH];
        #pragma unroll
        for (int c = 0; c < F4; ++c) {
            float4 v = mybuf[c];
            float4 s;
            #define LIF_STEP(XV, SV)                                   \
                do {                                                   \
                    float t1 = __fmul_rn(mem, beta);                   \
                    float t2 = __fadd_rn(t1, (XV));                    \
                    mem = __fadd_rn(t2, -rst);                         \
                    float spk = (mem > vth) ? 1.0f : 0.0f;             \
                    (SV) = spk;                                        \
                    rst = (mem > vth) ? vth : 0.0f;                    \
                } while (0)
            LIF_STEP(v.x, s.x);
            LIF_STEP(v.y, s.y);
            LIF_STEP(v.z, s.z);
            LIF_STEP(v.w, s.w);
            #undef LIF_STEP
            mybuf[c] = s;                         // in-place spike staging
        }
        __syncthreads();

        // ---- coalesced write-through store of tile `it` ----
        {
            const int tcol0 = it * F4;
            #pragma unroll
            for (int i = 0; i < F4; ++i) {
                int idx = i * NT + tid;
                int row = idx >> 3;
                int col = idx & 7;
                stwt(og + (size_t)(r0 + row) * row_f4 + tcol0 + col,
                     tile[b][row * PITCH + col]);
            }
        }
        __syncthreads();                          // LDS of buf done before refill

        // ---- refill buf b with tile it+3; always commit a group ----
        const int ip = it + NBUF;
        if (ip < NTILES) {
            const int tcol0 = ip * F4;
            uint32_t sbase = (uint32_t)__cvta_generic_to_shared(&tile[b][0]);
            #pragma unroll
            for (int i = 0; i < F4; ++i) {
                int idx = i * NT + tid;
                int row = idx >> 3;
                int col = idx & 7;
                cp16(sbase + (uint32_t)(row * PITCH + col) * 16u,
                     xg + (size_t)(r0 + row) * row_f4 + tcol0 + col);
            }
        }
        cp_commit();

        b = (b == NBUF - 1) ? 0 : b + 1;
    }
}

extern "C" void kernel_launch(void* const* d_in, const int* in_sizes, int n_in,
                              void* d_out, int out_size)
{
    const float* x    = (const float*)d_in[0];  // (128, 512, 1024) fp32
    const float* beta = (const float*)d_in[1];  // scalar fp32
    const float* vth  = (const float*)d_in[2];  // (512,) fp32
    float* out        = (float*)d_out;          // (128, 512, 1024) fp32

    lif_kernel<<<(Bdim * Cdim) / NT, NT>>>(x, beta, vth, out);
}

// round 5
// speedup vs baseline: 1.0389x; 1.0389x over previous
#include <cuda_runtime.h>
#include <cstdint>

// Spiking1DLIFLayer: B=128, C=512, T=1024  (row=(b,c), serial recurrence over T)
//   mem = (mem*beta + x[t]) - spk_prev*Vth[c] ;  spk = mem > Vth[c]
// Pure HBM-bound stream (256MB in + 256MB out).
// R4: write-through (st.global.wt) spike stores — each output line is written
// exactly once and never re-read, so L2 dirty-accumulation only hurts: in
// graph-replay steady state the previous launch's ~100MB dirty backlog drains
// into the next launch's read burst. .wt drains writes continuously instead.
// Pipeline: 1 warp/block, cp.async.cg triple-buffered, conflict-free smem.
// Numerics bit-identical to reference (rel_err 0.0 in R1-R3).

#define Bdim 128
#define Cdim 512
#define Tdim 1024
#define NT    32                 // threads per block == rows per block (1 warp)
#define TS    32                 // time-tile (floats)
#define F4    (TS / 4)           // 8 float4 per row per tile
#define PITCH (F4 + 1)           // 9 float4 -> conflict-free row access
#define NBUF  3
#define NTILES (Tdim / TS)       // 32

__device__ __forceinline__ void cp16(uint32_t dst_smem, const float4* src) {
    asm volatile("cp.async.cg.shared.global [%0], [%1], 16;\n"
                 :: "r"(dst_smem), "l"(src));
}
__device__ __forceinline__ void cp_commit() {
    asm volatile("cp.async.commit_group;\n");
}
__device__ __forceinline__ void cp_wait2() {
    asm volatile("cp.async.wait_group 2;\n");
}
__device__ __forceinline__ void stwt(float4* p, float4 v) {
    asm volatile("st.global.wt.v4.f32 [%0], {%1, %2, %3, %4};\n"
                 :: "l"(p), "f"(v.x), "f"(v.y), "f"(v.z), "f"(v.w)
                 : "memory");
}

__global__ void __launch_bounds__(NT, 16)
lif_kernel(const float* __restrict__ x,
           const float* __restrict__ beta_p,
           const float* __restrict__ vth_p,
           float* __restrict__ out)
{
    __shared__ float4 tile[NBUF][NT * PITCH];

    const int tid = threadIdx.x;
    const int r0  = blockIdx.x * NT;
    const float beta = __ldg(beta_p);
    const float vth  = __ldg(vth_p + ((r0 + tid) & (Cdim - 1)));

    const float4* __restrict__ xg = (const float4*)x;
    float4* __restrict__ og = (float4*)out;
    const int row_f4 = Tdim / 4;                  // 256 float4 per global row

    // ---- prologue: preload tiles 0..2 ----
    #pragma unroll
    for (int p = 0; p < NBUF; ++p) {
        const int tcol0 = p * F4;
        uint32_t sbase = (uint32_t)__cvta_generic_to_shared(&tile[p][0]);
        #pragma unroll
        for (int i = 0; i < F4; ++i) {
            int idx = i * NT + tid;
            int row = idx >> 3;                   // idx / F4
            int col = idx & 7;                    // idx % F4
            cp16(sbase + (uint32_t)(row * PITCH + col) * 16u,
                 xg + (size_t)(r0 + row) * row_f4 + tcol0 + col);
        }
        cp_commit();
    }

    float mem = 0.0f;
    float rst = 0.0f;
    int b = 0;

    for (int it = 0; it < NTILES; ++it) {
        cp_wait2();                               // tile `it` landed
        __syncthreads();                          // nw=1: cheap, warp-visibility

        // ---- recurrence: thread owns row `tid`, 32 steps from smem ----
        float4* mybuf = &tile[b][tid * PITCH];
        #pragma unroll
        for (int c = 0; c < F4; ++c) {
            float4 v = mybuf[c];
            float4 s;
            #define LIF_STEP(XV, SV)                                   \
                do {                                                   \
                    float t1 = __fmul_rn(mem, beta);                   \
                    float t2 = __fadd_rn(t1, (XV));                    \
                    mem = __fadd_rn(t2, -rst);                         \
                    float spk = (mem > vth) ? 1.0f : 0.0f;             \
                    (SV) = spk;                                        \
                    rst = (mem > vth) ? vth : 0.0f;                    \
                } while (0)
            LIF_STEP(v.x, s.x);
            LIF_STEP(v.y, s.y);
            LIF_STEP(v.z, s.z);
            LIF_STEP(v.w, s.w);
            #undef LIF_STEP
            mybuf[c] = s;                         // in-place spike staging
        }
        __syncthreads();

        // ---- coalesced write-through store of tile `it` ----
        {
            const int tcol0 = it * F4;
            #pragma unroll
            for (int i = 0; i < F4; ++i) {
                int idx = i * NT + tid;
                int row = idx >> 3;
                int col = idx & 7;
                stwt(og + (size_t)(r0 + row) * row_f4 + tcol0 + col,
                     tile[b][row * PITCH + col]);
            }
        }
        __syncthreads();                          // LDS of buf done before refill

        // ---- refill buf b with tile it+3; always commit a group ----
        const int ip = it + NBUF;
        if (ip < NTILES) {
            const int tcol0 = ip * F4;
            uint32_t sbase = (uint32_t)__cvta_generic_to_shared(&tile[b][0]);
            #pragma unroll
            for (int i = 0; i < F4; ++i) {
                int idx = i * NT + tid;
                int row = idx >> 3;
                int col = idx & 7;
                cp16(sbase + (uint32_t)(row * PITCH + col) * 16u,
                     xg + (size_t)(r0 + row) * row_f4 + tcol0 + col);
            }
        }
        cp_commit();

        b = (b == NBUF - 1) ? 0 : b + 1;
    }
}

extern "C" void kernel_launch(void* const* d_in, const int* in_sizes, int n_in,
                              void* d_out, int out_size)
{
    const float* x    = (const float*)d_in[0];  // (128, 512, 1024) fp32
    const float* beta = (const float*)d_in[1];  // scalar fp32
    const float* vth  = (const float*)d_in[2];  // (512,) fp32
    float* out        = (float*)d_out;          // (128, 512, 1024) fp32

    lif_kernel<<<(Bdim * Cdim) / NT, NT>>>(x, beta, vth, out);
}